// round 8
// baseline (speedup 1.0000x reference)
#include <cuda_runtime.h>

// x [B=8, C=64, T=32, H=56, W=56], window 7, eps 1e-5.
#define BB    8
#define CC    64
#define TT    32
#define HWV   (56 * 56)              // 3136 floats per plane
#define HW4   (HWV / 4)              // 784 float4 per (b,c,t) plane
#define NBC   (BB * CC)              // 512 (b,c) slabs
#define NCOL  (NBC * HW4)            // 401408 float4-columns total
#define BS    256                    // threads per block
#define NBLK  (NCOL / BS)            // 1568 blocks, exact
#define SLAB  (TT * HW4)             // 25088 float4 per (b,c) slab
#define NPC   ((double)(BB * TT * HWV))  // 802816 elements per channel

// Deterministic scratch (no float atomics). Per-block two-segment partials:
// [blk][0]=sum_lo, [1]=sumsq_lo, [2]=sum_hi, [3]=sumsq_hi  (sums of u = rp/2)
__device__ double g_part[NBLK * 4];
__device__ float  g_scale[CC];   // holds 2*gamma/std (factor 2 folds rp=2u)
__device__ float  g_bias[CC];
__device__ float  g_k[2];

// u = rp/2 = 3*(x_t - x_{t-6}) + 2*(x_{t-1} - x_{t-5}) + (x_{t-2} - x_{t-4})
// window regs: w0..w5 = x_{t-6}..x_{t-1}
#define U_COMP(comp, xv)                                                      \
    fmaf(3.0f, (xv).comp - w0.comp,                                           \
         fmaf(2.0f, w5.comp - w1.comp, w4.comp - w2.comp))

// ---------------- Pass 1: per-column rp stats, two-segment reduce ----------
__global__ __launch_bounds__(BS) void datt_pass1(const float4* __restrict__ x4) {
    const int cid = blockIdx.x * BS + threadIdx.x;   // < NCOL exactly
    const int bc  = cid / HW4;
    const int p   = cid - bc * HW4;
    const float4* __restrict__ q = x4 + (size_t)bc * SLAB + p;

    float s = 0.0f, ss = 0.0f;
    float4 w0 = {0.f, 0.f, 0.f, 0.f};
    float4 w1 = w0, w2 = w0, w3 = w0, w4 = w0, w5 = w0;
#pragma unroll
    for (int t = 0; t < TT; t++) {
        float4 xv = q[t * HW4];
        float ux = U_COMP(x, xv);
        float uy = U_COMP(y, xv);
        float uz = U_COMP(z, xv);
        float uw = U_COMP(w, xv);
        s += (ux + uy) + (uz + uw);
        ss = fmaf(ux, ux, ss);
        ss = fmaf(uy, uy, ss);
        ss = fmaf(uz, uz, ss);
        ss = fmaf(uw, uw, ss);
        w0 = w1; w1 = w2; w2 = w3; w3 = w4; w4 = w5; w5 = xv;
    }

    // Two-segment deterministic reduction: a 256-thread block spans at most
    // one bc boundary (256 < 784). Segment 0 = bc_lo, segment 1 = bc_lo + 1.
    const int bc_lo = (blockIdx.x * BS) / HW4;
    const bool hi = (bc != bc_lo);
    double s0 = hi ? 0.0 : (double)s;
    double q0 = hi ? 0.0 : (double)ss;
    double s1 = hi ? (double)s : 0.0;
    double q1 = hi ? (double)ss : 0.0;
#pragma unroll
    for (int o = 16; o > 0; o >>= 1) {
        s0 += __shfl_down_sync(0xFFFFFFFFu, s0, o);
        q0 += __shfl_down_sync(0xFFFFFFFFu, q0, o);
        s1 += __shfl_down_sync(0xFFFFFFFFu, s1, o);
        q1 += __shfl_down_sync(0xFFFFFFFFu, q1, o);
    }
    __shared__ double sh[8][4];
    const int lane = threadIdx.x & 31, wid = threadIdx.x >> 5;
    if (lane == 0) { sh[wid][0] = s0; sh[wid][1] = q0; sh[wid][2] = s1; sh[wid][3] = q1; }
    __syncthreads();
    if (threadIdx.x == 0) {
        double a0 = 0, b0 = 0, a1 = 0, b1 = 0;
#pragma unroll
        for (int i = 0; i < 8; i++) {
            a0 += sh[i][0]; b0 += sh[i][1]; a1 += sh[i][2]; b1 += sh[i][3];
        }
        double* g = g_part + (size_t)blockIdx.x * 4;
        g[0] = a0; g[1] = b0; g[2] = a1; g[3] = b1;
    }
}

// ---------------- Finalize: gather segments -> per-channel BN affine -------
__global__ void datt_finalize(const float* __restrict__ gamma,
                              const float* __restrict__ beta,
                              const float* __restrict__ rpw) {
    __shared__ double sh[NBC][2];
    const int bc = threadIdx.x;          // 512 threads, one per (b,c) slab
    double S = 0.0, SS = 0.0;
    const int k0 = (bc * HW4) / BS;
    const int k1 = (bc * HW4 + HW4 - 1) / BS;
    for (int k = k0; k <= k1; k++) {
        const int lo = (k * BS) / HW4;
        const int hh = (k * BS + BS - 1) / HW4;
        const double* g = g_part + (size_t)k * 4;
        if (lo == bc) { S += g[0]; SS += g[1]; }
        if (hh == bc) { S += g[2]; SS += g[3]; }  // seg1 == 0 when lo==hh
    }
    sh[bc][0] = S; sh[bc][1] = SS;
    __syncthreads();
    if (threadIdx.x < CC) {
        const int c = threadIdx.x;
        double a = 0.0, b = 0.0;
#pragma unroll
        for (int bb = 0; bb < BB; bb++) { a += sh[bb * CC + c][0]; b += sh[bb * CC + c][1]; }
        // sums were of u = rp/2:  sum_rp = 2a,  sumsq_rp = 4b
        const double mean = 2.0 * a / NPC;
        const double var  = 4.0 * b / NPC - mean * mean;
        const double sc   = (double)gamma[c] / sqrt(var + 1e-5);
        g_scale[c] = (float)(2.0 * sc);                     // applied to u
        g_bias[c]  = (float)((double)beta[c] - mean * sc);
    }
    if (threadIdx.x == 0) {
        g_k[0] = rpw[0] + rpw[1];   // k1 = rpw0 + rpw1
        g_k[1] = rpw[1];            // k2
    }
}

// ---------------- Pass 2: recompute rp, BN+ReLU+gate+mix, write ------------
// out = x * (k1 + k2 * relu(sc2*u + bi)).  Reverse block order for L2 reuse.
__global__ __launch_bounds__(BS) void datt_pass2(const float4* __restrict__ x4,
                                                 float4* __restrict__ o4) {
    const int cid = (NBLK - 1 - blockIdx.x) * BS + threadIdx.x;
    const int bc  = cid / HW4;
    const int c   = bc & (CC - 1);
    const float sc2 = g_scale[c];
    const float bi  = g_bias[c];
    const float k1  = g_k[0];
    const float k2  = g_k[1];

    const size_t off = (size_t)bc * SLAB + (cid - bc * HW4);
    const float4* __restrict__ q = x4 + off;
    float4* __restrict__ o = o4 + off;

    float4 w0 = {0.f, 0.f, 0.f, 0.f};
    float4 w1 = w0, w2 = w0, w3 = w0, w4 = w0, w5 = w0;
#pragma unroll
    for (int t = 0; t < TT; t++) {
        float4 xv = __ldcs(q + t * HW4);   // streaming: last use of this line
        float yx = fmaxf(fmaf(U_COMP(x, xv), sc2, bi), 0.0f);
        float yy = fmaxf(fmaf(U_COMP(y, xv), sc2, bi), 0.0f);
        float yz = fmaxf(fmaf(U_COMP(z, xv), sc2, bi), 0.0f);
        float yw = fmaxf(fmaf(U_COMP(w, xv), sc2, bi), 0.0f);
        float4 ov;
        ov.x = xv.x * fmaf(k2, yx, k1);
        ov.y = xv.y * fmaf(k2, yy, k1);
        ov.z = xv.z * fmaf(k2, yz, k1);
        ov.w = xv.w * fmaf(k2, yw, k1);
        __stcs(o + t * HW4, ov);           // streaming store: keep L2 for x
        w0 = w1; w1 = w2; w2 = w3; w3 = w4; w4 = w5; w5 = xv;
    }
}

extern "C" void kernel_launch(void* const* d_in, const int* in_sizes, int n_in,
                              void* d_out, int out_size) {
    const float4* x4   = (const float4*)d_in[0];  // [8,64,32,56,56]
    const float* gamma = (const float*)d_in[1];   // [64]
    const float* beta  = (const float*)d_in[2];   // [64]
    const float* rpw   = (const float*)d_in[3];   // [2]
    float4* out4 = (float4*)d_out;

    datt_pass1<<<NBLK, BS>>>(x4);
    datt_finalize<<<1, NBC>>>(gamma, beta, rpw);
    datt_pass2<<<NBLK, BS>>>(x4, out4);
}

// round 9
// speedup vs baseline: 1.0897x; 1.0897x over previous
#include <cuda_runtime.h>

// x [B=8, C=64, T=32, H=56, W=56], window 7, eps 1e-5.
#define BB    8
#define CC    64
#define TT    32
#define HWV   (56 * 56)              // 3136 floats per plane
#define HW4   (HWV / 4)              // 784 float4 per (b,c,t) plane
#define NBC   (BB * CC)              // 512 (b,c) slabs
#define NCOL  (NBC * HW4)            // 401408 float4-columns total
#define BS    256                    // threads per block
#define NBLK  (NCOL / BS)            // 1568 blocks, exact
#define SLAB  (TT * HW4)             // 25088 float4 per (b,c) slab
#define NPC   ((double)(BB * TT * HWV))  // 802816 elements per channel

// Deterministic scratch (no float atomics). Per-block two-segment fp32
// partials: [blk][0]=sum_lo, [1]=sumsq_lo, [2]=sum_hi, [3]=sumsq_hi
// (sums of u = rp/2). Promoted to double only in the finalize gather.
__device__ float g_part[NBLK * 4];
__device__ float g_scale[CC];   // holds 2*gamma/std (factor 2 folds rp=2u)
__device__ float g_bias[CC];
__device__ float g_k[2];

// u = rp/2 = 3*(x_t - x_{t-6}) + 2*(x_{t-1} - x_{t-5}) + (x_{t-2} - x_{t-4})
// window regs: w0..w5 = x_{t-6}..x_{t-1}
#define U_COMP(comp, xv)                                                      \
    fmaf(3.0f, (xv).comp - w0.comp,                                           \
         fmaf(2.0f, w5.comp - w1.comp, w4.comp - w2.comp))

// ---------------- Pass 1: per-column rp stats, cheap fp32 two-segment reduce
__global__ __launch_bounds__(BS) void datt_pass1(const float4* __restrict__ x4) {
    const int cid = blockIdx.x * BS + threadIdx.x;   // < NCOL exactly
    const int bc  = cid / HW4;
    const int p   = cid - bc * HW4;
    const float4* __restrict__ q = x4 + (size_t)bc * SLAB + p;

    float s = 0.0f, ss = 0.0f;
    float4 w0 = {0.f, 0.f, 0.f, 0.f};
    float4 w1 = w0, w2 = w0, w3 = w0, w4 = w0, w5 = w0;
#pragma unroll
    for (int t = 0; t < TT; t++) {
        float4 xv = q[t * HW4];
        float ux = U_COMP(x, xv);
        float uy = U_COMP(y, xv);
        float uz = U_COMP(z, xv);
        float uw = U_COMP(w, xv);
        s += (ux + uy) + (uz + uw);
        ss = fmaf(ux, ux, ss);
        ss = fmaf(uy, uy, ss);
        ss = fmaf(uz, uz, ss);
        ss = fmaf(uw, uw, ss);
        w0 = w1; w1 = w2; w2 = w3; w3 = w4; w4 = w5; w5 = xv;
    }

    // Two-segment fp32 reduction: a 256-thread block spans at most one bc
    // boundary (256 < 784). Segment 0 = bc_lo, segment 1 = bc_lo + 1.
    const int bc_lo = (blockIdx.x * BS) / HW4;
    const bool hi = (bc != bc_lo);
    float s0 = hi ? 0.0f : s;
    float q0 = hi ? 0.0f : ss;
    float s1 = hi ? s : 0.0f;
    float q1 = hi ? ss : 0.0f;
#pragma unroll
    for (int o = 16; o > 0; o >>= 1) {
        s0 += __shfl_down_sync(0xFFFFFFFFu, s0, o);
        q0 += __shfl_down_sync(0xFFFFFFFFu, q0, o);
        s1 += __shfl_down_sync(0xFFFFFFFFu, s1, o);
        q1 += __shfl_down_sync(0xFFFFFFFFu, q1, o);
    }
    __shared__ float sh[8][4];
    const int lane = threadIdx.x & 31, wid = threadIdx.x >> 5;
    if (lane == 0) { sh[wid][0] = s0; sh[wid][1] = q0; sh[wid][2] = s1; sh[wid][3] = q1; }
    __syncthreads();
    if (threadIdx.x == 0) {
        float a0 = 0.f, b0 = 0.f, a1 = 0.f, b1 = 0.f;
#pragma unroll
        for (int i = 0; i < 8; i++) {
            a0 += sh[i][0]; b0 += sh[i][1]; a1 += sh[i][2]; b1 += sh[i][3];
        }
        float4 pv = {a0, b0, a1, b1};
        *reinterpret_cast<float4*>(g_part + (size_t)blockIdx.x * 4) = pv;
    }
}

// ---------------- Finalize: gather fp32 segments -> per-channel BN affine --
__global__ void datt_finalize(const float* __restrict__ gamma,
                              const float* __restrict__ beta,
                              const float* __restrict__ rpw) {
    __shared__ double sh[NBC][2];
    const int bc = threadIdx.x;          // 512 threads, one per (b,c) slab
    double S = 0.0, SS = 0.0;
    const int k0 = (bc * HW4) / BS;
    const int k1 = (bc * HW4 + HW4 - 1) / BS;
    for (int k = k0; k <= k1; k++) {
        const int lo = (k * BS) / HW4;
        const int hh = (k * BS + BS - 1) / HW4;
        const float* g = g_part + (size_t)k * 4;
        if (lo == bc) { S += (double)g[0]; SS += (double)g[1]; }
        if (hh == bc) { S += (double)g[2]; SS += (double)g[3]; }  // seg1==0 if lo==hh
    }
    sh[bc][0] = S; sh[bc][1] = SS;
    __syncthreads();
    if (threadIdx.x < CC) {
        const int c = threadIdx.x;
        double a = 0.0, b = 0.0;
#pragma unroll
        for (int bb = 0; bb < BB; bb++) { a += sh[bb * CC + c][0]; b += sh[bb * CC + c][1]; }
        // sums were of u = rp/2:  sum_rp = 2a,  sumsq_rp = 4b
        const double mean = 2.0 * a / NPC;
        const double var  = 4.0 * b / NPC - mean * mean;
        const double sc   = (double)gamma[c] / sqrt(var + 1e-5);
        g_scale[c] = (float)(2.0 * sc);                     // applied to u
        g_bias[c]  = (float)((double)beta[c] - mean * sc);
    }
    if (threadIdx.x == 0) {
        g_k[0] = rpw[0] + rpw[1];   // k1 = rpw0 + rpw1
        g_k[1] = rpw[1];            // k2
    }
}

// ---------------- Pass 2: recompute rp, BN+ReLU+gate+mix, write ------------
// out = x * (k1 + k2 * relu(sc2*u + bi)).  Reverse block order for L2 reuse.
__global__ __launch_bounds__(BS) void datt_pass2(const float4* __restrict__ x4,
                                                 float4* __restrict__ o4) {
    const int cid = (NBLK - 1 - blockIdx.x) * BS + threadIdx.x;
    const int bc  = cid / HW4;
    const int c   = bc & (CC - 1);
    const float sc2 = g_scale[c];
    const float bi  = g_bias[c];
    const float k1  = g_k[0];
    const float k2  = g_k[1];

    const size_t off = (size_t)bc * SLAB + (cid - bc * HW4);
    const float4* __restrict__ q = x4 + off;
    float4* __restrict__ o = o4 + off;

    float4 w0 = {0.f, 0.f, 0.f, 0.f};
    float4 w1 = w0, w2 = w0, w3 = w0, w4 = w0, w5 = w0;
#pragma unroll
    for (int t = 0; t < TT; t++) {
        float4 xv = __ldcs(q + t * HW4);   // streaming: last use of this line
        float yx = fmaxf(fmaf(U_COMP(x, xv), sc2, bi), 0.0f);
        float yy = fmaxf(fmaf(U_COMP(y, xv), sc2, bi), 0.0f);
        float yz = fmaxf(fmaf(U_COMP(z, xv), sc2, bi), 0.0f);
        float yw = fmaxf(fmaf(U_COMP(w, xv), sc2, bi), 0.0f);
        float4 ov;
        ov.x = xv.x * fmaf(k2, yx, k1);
        ov.y = xv.y * fmaf(k2, yy, k1);
        ov.z = xv.z * fmaf(k2, yz, k1);
        ov.w = xv.w * fmaf(k2, yw, k1);
        __stcs(o + t * HW4, ov);           // streaming store: keep L2 for x
        w0 = w1; w1 = w2; w2 = w3; w3 = w4; w4 = w5; w5 = xv;
    }
}

extern "C" void kernel_launch(void* const* d_in, const int* in_sizes, int n_in,
                              void* d_out, int out_size) {
    const float4* x4   = (const float4*)d_in[0];  // [8,64,32,56,56]
    const float* gamma = (const float*)d_in[1];   // [64]
    const float* beta  = (const float*)d_in[2];   // [64]
    const float* rpw   = (const float*)d_in[3];   // [2]
    float4* out4 = (float4*)d_out;

    datt_pass1<<<NBLK, BS>>>(x4);
    datt_finalize<<<1, NBC>>>(gamma, beta, rpw);
    datt_pass2<<<NBLK, BS>>>(x4, out4);
}